// round 5
// baseline (speedup 1.0000x reference)
#include <cuda_runtime.h>

#define VOL 262144   // 64*64*64 voxels

typedef unsigned long long u64;

__device__ __forceinline__ u64 pk2(float lo, float hi) {
    u64 r; asm("mov.b64 %0,{%1,%2};" : "=l"(r) : "f"(lo), "f"(hi)); return r;
}
__device__ __forceinline__ void upk2(u64 v, float& lo, float& hi) {
    asm("mov.b64 {%0,%1},%2;" : "=f"(lo), "=f"(hi) : "l"(v));
}
__device__ __forceinline__ void fma2(u64& d, u64 a, u64 b) {
    asm("fma.rn.f32x2 %0,%1,%2,%0;" : "+l"(d) : "l"(a), "l"(b));
}
__device__ __forceinline__ u64 mul2(u64 a, u64 b) {
    u64 r; asm("mul.rn.f32x2 %0,%1,%2;" : "=l"(r) : "l"(a), "l"(b)); return r;
}
__device__ __forceinline__ u64 add2(u64 a, u64 b) {
    u64 r; asm("add.rn.f32x2 %0,%1,%2;" : "=l"(r) : "l"(a), "l"(b)); return r;
}

// ---------------- device-global precomputed weights (scratch; no allocs) ----------------
__device__ __align__(16) float g_WQKVT[128 * 384]; // folded qkv weights TRANSPOSED: [c][o]
__device__ __align__(16) float g_QB[384];          // folded qkv bias
__device__ __align__(16) float g_P[64 * 128];      // proj_w[:64] + proj_w[64:]  [c][k]
__device__ float g_PB[64];                         // proj_b[:64] + proj_b[64:]
__device__ __align__(16) float g_BIAS[4 * 64 * 64];// dense rel-pos bias [h][i][j]

// ---------------- prep kernel: fold weights, gather bias table ----------------
__global__ void prep_kernel(const float* __restrict__ conv_w, const float* __restrict__ conv_b,
                            const float* __restrict__ trans_w, const float* __restrict__ trans_b,
                            const float* __restrict__ qkv_w, const float* __restrict__ qkv_b,
                            const float* __restrict__ proj_w, const float* __restrict__ proj_b,
                            const float* __restrict__ table, const int* __restrict__ ridx)
{
    int id = blockIdx.x * blockDim.x + threadIdx.x;
    if (id < 49152) {                       // WQKVT[c][o]
        int c = id / 384, o = id % 384;
        float s = 0.f;
        if (c < 64) {
            const float* qw = qkv_w + o * 128;
            #pragma unroll 8
            for (int m = 0; m < 64; m++) s += qw[m] * conv_w[m * 64 + c];
        } else {
            const float* qw = qkv_w + o * 128 + 64;
            int cc = c - 64;
            #pragma unroll 8
            for (int m = 0; m < 64; m++) s += qw[m] * trans_w[m * 64 + cc];
        }
        g_WQKVT[id] = s;
    } else if (id < 49536) {                // QB
        int o = id - 49152;
        float s = qkv_b[o];
        const float* qw = qkv_w + o * 128;
        #pragma unroll 8
        for (int m = 0; m < 64; m++) s += qw[m] * conv_b[m] + qw[64 + m] * trans_b[m];
        g_QB[o] = s;
    } else if (id < 57728) {                // P[c][k]
        int p = id - 49536;
        int c = p >> 7, k = p & 127;
        g_P[p] = proj_w[c * 128 + k] + proj_w[(c + 64) * 128 + k];
    } else if (id < 57792) {                // PB
        int c = id - 57728;
        g_PB[c] = proj_b[c] + proj_b[c + 64];
    } else if (id < 74176) {                // BIAS[h][i][j]
        int x = id - 57792;
        int h = x >> 12, ij = x & 4095;
        g_BIAS[x] = table[ridx[ij] * 4 + h];
    }
}

// ---------------- fused per-window kernel (512 threads) ----------------
// smem layout (floats):
//   feat : [128] x 17 float4                              off 0
//   qkv  : 64 tokens * 96 16B-units, XOR-swizzled         off 8704
//   wt   : [c:128] x 33 float4 (o-vectorized)             off 33280 (spans to 50176)
//   outs : [64] x 33 float4 (aliases wt lower half)       off 33280
//   ps   : [64] x 33 float4 (aliases wt upper half)       off 41728
// total 50176 floats = 200704 bytes

__global__ void __launch_bounds__(512, 1)
fused_attn_kernel(const float* __restrict__ conv_feat,
                  const float* __restrict__ trans_feat,
                  float* __restrict__ out)
{
    extern __shared__ float sm[];
    float* feat = sm;
    float4* feat4 = (float4*)sm;                    // stride 17
    ulonglong2* qkvu  = (ulonglong2*)(sm + 8704);   // stride 96 per token
    ulonglong2* wtu   = (ulonglong2*)(sm + 33280);  // stride 33 per c
    ulonglong2* outsu = (ulonglong2*)(sm + 33280);  // stride 33 per token
    ulonglong2* psu   = (ulonglong2*)(sm + 41728);  // stride 33 per channel
    float4* wt4 = (float4*)(sm + 33280);
    float4* ps4 = (float4*)(sm + 41728);

    const int tid = threadIdx.x;
    const int wb = blockIdx.x;
    const int base = ((wb >> 8) * 4) * 4096 + (((wb >> 4) & 15) * 4) * 64 + (wb & 15) * 4;

    // ---- Phase 1: load cf/tf window tiles (channel-major [c][t]) ----
    #pragma unroll
    for (int k = 0; k < 4; k++) {
        int v = k * 512 + tid;              // 0..2047 float4s
        int vv = v & 1023;
        int c = vv >> 4;
        int r16 = vv & 15;                  // (dz,dy)
        const float* src = (v < 1024) ? conv_feat : trans_feat;
        float4 val = *(const float4*)(src + (size_t)c * VOL + base + (r16 >> 2) * 4096 + (r16 & 3) * 64);
        int row = (v < 1024) ? c : (64 + c);
        feat4[row * 17 + r16] = val;
    }
    __syncthreads();

    // ---- Phase 2: qkv[t][o] = sum_c WQKVT[c][o] * feat[c][t] + QB[o] ----
    // warp = (token-quarter tq, o-quarter oq); lane = (lx: token sub, ly: o sub)
    const int wid  = tid >> 5, lane = tid & 31;
    const int tq = wid & 3, oq = wid >> 2;
    const int lx = lane & 3, ly = lane >> 2;
    const int txg = tq * 4 + lx;            // token group (4 tokens), 0..15
    const int sxp = txg & 7;                // swizzle key = (t>>2)&7
    const float4* gW4 = (const float4*)g_WQKVT;  // [c][96] float4

    for (int ob = 0; ob < 384; ob += 128) {
        // stage weight chunk: wt4[c*33 + o4] = WQKVT4[c*96 + ob/4 + o4]
        #pragma unroll
        for (int k = 0; k < 8; k++) {
            int f = k * 512 + tid;          // 0..4095
            int c = f >> 5, o4 = f & 31;
            wt4[c * 33 + o4] = gW4[c * 96 + (ob >> 2) + o4];
        }
        __syncthreads();

        // 8 outputs (2 pairs) x 4 tokens per thread
        u64 acc[2][4];
        {
            float4 qb4 = *(const float4*)(g_QB + ob + oq * 32 + ly * 4);
            u64 b0 = pk2(qb4.x, qb4.y), b1 = pk2(qb4.z, qb4.w);
            #pragma unroll
            for (int m = 0; m < 4; m++) { acc[0][m] = b0; acc[1][m] = b1; }
        }
        #pragma unroll 4
        for (int c = 0; c < 128; c++) {
            float4 fv = feat4[c * 17 + txg];
            ulonglong2 wv = wtu[c * 33 + oq * 8 + ly];   // pairs (o0,o1),(o2,o3)
            u64 d0 = pk2(fv.x, fv.x), d1 = pk2(fv.y, fv.y);
            u64 d2 = pk2(fv.z, fv.z), d3 = pk2(fv.w, fv.w);
            fma2(acc[0][0], wv.x, d0); fma2(acc[1][0], wv.y, d0);
            fma2(acc[0][1], wv.x, d1); fma2(acc[1][1], wv.y, d1);
            fma2(acc[0][2], wv.x, d2); fma2(acc[1][2], wv.y, d2);
            fma2(acc[0][3], wv.x, d3); fma2(acc[1][3], wv.y, d3);
        }
        // swizzled conflict-free 16B stores
        {
            int u = (ob >> 2) + oq * 8 + ly;
            #pragma unroll
            for (int m = 0; m < 4; m++) {
                int t = txg * 4 + m;
                ulonglong2 st;
                st.x = acc[0][m]; st.y = acc[1][m];
                qkvu[t * 96 + (u ^ sxp)] = st;
            }
        }
        __syncthreads();
    }

    // ---- Phase 3: attention, 2 threads per (head,row), j-range split ----
    {
        const int jh  = tid & 1;           // j half: [jh*32, jh*32+32)
        const int idx = tid >> 1;
        const int h   = idx >> 6;          // warp-uniform
        const int ii  = idx & 63;
        const int isw = (ii >> 2) & 7;
        u64 qvp[16];                       // q pairs along d
        #pragma unroll
        for (int d4 = 0; d4 < 8; d4++) {
            ulonglong2 q = qkvu[ii * 96 + ((h * 8 + d4) ^ isw)];
            qvp[d4 * 2] = q.x; qvp[d4 * 2 + 1] = q.y;
        }
        float sc[32];
        const float4* brow4 = (const float4*)(g_BIAS + (h * 64 + ii) * 64 + jh * 32);
        #pragma unroll
        for (int j4 = 0; j4 < 8; j4++) {
            float4 b = brow4[j4];
            sc[j4 * 4 + 0] = b.x; sc[j4 * 4 + 1] = b.y;
            sc[j4 * 4 + 2] = b.z; sc[j4 * 4 + 3] = b.w;
        }
        const float scale = 0.17677669529663688f;  // 32^-0.5
        float rowmax = -1e30f;
        #pragma unroll
        for (int jj = 0; jj < 32; jj++) {
            int j = jh * 32 + jj;
            int jsw = (j >> 2) & 7;
            u64 a0 = 0ull, a1 = 0ull;
            #pragma unroll
            for (int d4 = 0; d4 < 8; d4++) {
                ulonglong2 kk = qkvu[j * 96 + ((32 + h * 8 + d4) ^ jsw)];
                fma2(a0, qvp[d4 * 2], kk.x);
                fma2(a1, qvp[d4 * 2 + 1], kk.y);
            }
            float l0, h0, l1, h1;
            upk2(a0, l0, h0); upk2(a1, l1, h1);
            float a = (l0 + h0) + (l1 + h1);
            sc[jj] = fmaf(a, scale, sc[jj]);
            rowmax = fmaxf(rowmax, sc[jj]);
        }
        rowmax = fmaxf(rowmax, __shfl_xor_sync(0xFFFFFFFFu, rowmax, 1));
        float ssum = 0.f;
        #pragma unroll
        for (int jj = 0; jj < 32; jj++) {
            sc[jj] = __expf(sc[jj] - rowmax);
            ssum += sc[jj];
        }
        ssum += __shfl_xor_sync(0xFFFFFFFFu, ssum, 1);
        float inv = 1.f / ssum;
        u64 ovp[16];
        #pragma unroll
        for (int d = 0; d < 16; d++) ovp[d] = 0ull;
        #pragma unroll
        for (int jj = 0; jj < 32; jj++) {
            int j = jh * 32 + jj;
            int jsw = (j >> 2) & 7;
            u64 p2 = pk2(sc[jj], sc[jj]);
            #pragma unroll
            for (int d4 = 0; d4 < 8; d4++) {
                ulonglong2 vv = qkvu[j * 96 + ((64 + h * 8 + d4) ^ jsw)];
                fma2(ovp[d4 * 2], p2, vv.x);
                fma2(ovp[d4 * 2 + 1], p2, vv.y);
            }
        }
        // combine partner halves (adjacent lanes)
        #pragma unroll
        for (int d = 0; d < 16; d++)
            ovp[d] = add2(ovp[d], __shfl_xor_sync(0xFFFFFFFFu, ovp[d], 1));
        u64 inv2 = pk2(inv, inv);
        // even thread stores d4 0..3, odd stores 4..7
        #pragma unroll
        for (int d4p = 0; d4p < 4; d4p++) {
            int d4 = jh * 4 + d4p;
            ulonglong2 st;
            st.x = mul2(ovp[d4 * 2], inv2);
            st.y = mul2(ovp[d4 * 2 + 1], inv2);
            outsu[ii * 33 + h * 8 + d4] = st;
        }
    }

    // stage P tile (ps region disjoint from outs & qkv)
    #pragma unroll
    for (int k = 0; k < 4; k++) {
        int f = k * 512 + tid;              // 0..2047
        ps4[(f >> 5) * 33 + (f & 31)] = *((const float4*)g_P + f);
    }
    __syncthreads();

    // ---- Phase 4: final[t][c] = sum_k outs[t][k]*P[c][k] + PB[c] + conv_feat[c][t] ----
    // executed by tid<256: 4 tokens (t = m*16+tx) x 4 channels (c = ty*4+r) per thread
    if (tid < 256) {
        const int tx = tid & 15;
        const int ty = tid >> 4;
        u64 acc2[4][4];
        #pragma unroll
        for (int r = 0; r < 4; r++)
            #pragma unroll
            for (int m = 0; m < 4; m++) acc2[r][m] = 0ull;

        #pragma unroll 4
        for (int k4 = 0; k4 < 32; k4++) {
            ulonglong2 pr[4], ovv[4];
            #pragma unroll
            for (int r = 0; r < 4; r++) pr[r] = psu[(ty * 4 + r) * 33 + k4];
            #pragma unroll
            for (int m = 0; m < 4; m++) ovv[m] = outsu[(m * 16 + tx) * 33 + k4];
            #pragma unroll
            for (int r = 0; r < 4; r++)
                #pragma unroll
                for (int m = 0; m < 4; m++) {
                    fma2(acc2[r][m], pr[r].x, ovv[m].x);
                    fma2(acc2[r][m], pr[r].y, ovv[m].y);
                }
        }
        int dy = tx >> 2, dx = tx & 3;
        #pragma unroll
        for (int r = 0; r < 4; r++) {
            int c = ty * 4 + r;
            float pb = g_PB[c];
            #pragma unroll
            for (int m = 0; m < 4; m++) {
                int t = m * 16 + tx;
                float lo, hi;
                upk2(acc2[r][m], lo, hi);
                float cf = feat[c * 68 + t];
                out[(size_t)c * VOL + base + m * 4096 + dy * 64 + dx] = (lo + hi) + pb + cf;
            }
        }
    }
}

// ---------------- launch ----------------
extern "C" void kernel_launch(void* const* d_in, const int* in_sizes, int n_in,
                              void* d_out, int out_size)
{
    const float* conv_feat  = (const float*)d_in[0];
    const float* trans_feat = (const float*)d_in[1];
    const float* conv_w     = (const float*)d_in[2];
    const float* conv_b     = (const float*)d_in[3];
    const float* trans_w    = (const float*)d_in[4];
    const float* trans_b    = (const float*)d_in[5];
    const float* qkv_w      = (const float*)d_in[6];
    const float* qkv_b      = (const float*)d_in[7];
    const float* proj_w     = (const float*)d_in[8];
    const float* proj_b     = (const float*)d_in[9];
    const float* table      = (const float*)d_in[10];
    const int*   ridx       = (const int*)d_in[11];
    float* o = (float*)d_out;

    cudaFuncSetAttribute(fused_attn_kernel, cudaFuncAttributeMaxDynamicSharedMemorySize, 200704);

    prep_kernel<<<290, 256>>>(conv_w, conv_b, trans_w, trans_b,
                              qkv_w, qkv_b, proj_w, proj_b, table, ridx);
    fused_attn_kernel<<<4096, 512, 200704>>>(conv_feat, trans_feat, o);
}

// round 6
// speedup vs baseline: 1.0541x; 1.0541x over previous
#include <cuda_runtime.h>

#define VOL 262144   // 64*64*64 voxels

typedef unsigned long long u64;

__device__ __forceinline__ u64 pk2(float lo, float hi) {
    u64 r; asm("mov.b64 %0,{%1,%2};" : "=l"(r) : "f"(lo), "f"(hi)); return r;
}
__device__ __forceinline__ void upk2(u64 v, float& lo, float& hi) {
    asm("mov.b64 {%0,%1},%2;" : "=f"(lo), "=f"(hi) : "l"(v));
}
__device__ __forceinline__ void fma2(u64& d, u64 a, u64 b) {
    asm("fma.rn.f32x2 %0,%1,%2,%0;" : "+l"(d) : "l"(a), "l"(b));
}
__device__ __forceinline__ u64 mul2(u64 a, u64 b) {
    u64 r; asm("mul.rn.f32x2 %0,%1,%2;" : "=l"(r) : "l"(a), "l"(b)); return r;
}
__device__ __forceinline__ u64 add2(u64 a, u64 b) {
    u64 r; asm("add.rn.f32x2 %0,%1,%2;" : "=l"(r) : "l"(a), "l"(b)); return r;
}

// ---------------- device-global precomputed weights (scratch; no allocs) ----------------
__device__ __align__(16) float g_WQKVT[128 * 384]; // folded qkv weights TRANSPOSED: [c][o]
__device__ __align__(16) float g_QB[384];          // folded qkv bias
__device__ __align__(16) float g_P[64 * 128];      // proj_w[:64] + proj_w[64:]  [c][k]
__device__ float g_PB[64];                         // proj_b[:64] + proj_b[64:]
__device__ __align__(16) float g_BIAS[4 * 64 * 64];// dense rel-pos bias [h][i][j]

// ---------------- prep kernel: fold weights, gather bias table ----------------
__global__ void prep_kernel(const float* __restrict__ conv_w, const float* __restrict__ conv_b,
                            const float* __restrict__ trans_w, const float* __restrict__ trans_b,
                            const float* __restrict__ qkv_w, const float* __restrict__ qkv_b,
                            const float* __restrict__ proj_w, const float* __restrict__ proj_b,
                            const float* __restrict__ table, const int* __restrict__ ridx)
{
    int id = blockIdx.x * blockDim.x + threadIdx.x;
    if (id < 49152) {                       // WQKVT[c][o]
        int c = id / 384, o = id % 384;
        float s = 0.f;
        if (c < 64) {
            const float* qw = qkv_w + o * 128;
            #pragma unroll 8
            for (int m = 0; m < 64; m++) s += qw[m] * conv_w[m * 64 + c];
        } else {
            const float* qw = qkv_w + o * 128 + 64;
            int cc = c - 64;
            #pragma unroll 8
            for (int m = 0; m < 64; m++) s += qw[m] * trans_w[m * 64 + cc];
        }
        g_WQKVT[id] = s;
    } else if (id < 49536) {                // QB
        int o = id - 49152;
        float s = qkv_b[o];
        const float* qw = qkv_w + o * 128;
        #pragma unroll 8
        for (int m = 0; m < 64; m++) s += qw[m] * conv_b[m] + qw[64 + m] * trans_b[m];
        g_QB[o] = s;
    } else if (id < 57728) {                // P[c][k]
        int p = id - 49536;
        int c = p >> 7, k = p & 127;
        g_P[p] = proj_w[c * 128 + k] + proj_w[(c + 64) * 128 + k];
    } else if (id < 57792) {                // PB
        int c = id - 57728;
        g_PB[c] = proj_b[c] + proj_b[c + 64];
    } else if (id < 74176) {                // BIAS[h][i][j]
        int x = id - 57792;
        int h = x >> 12, ij = x & 4095;
        g_BIAS[x] = table[ridx[ij] * 4 + h];
    }
}

// ---------------- fused per-window kernel (512 threads) ----------------
// smem layout (floats):
//   feat : [128] x 17 float4                              off 0
//   qkv  : 64 tokens * 96 16B-units, XOR-swizzled         off 8704
//   wt   : [c:128] x 33 float4 (o-vectorized)             off 33280 (spans to 50176)
//   outs : [64] x 33 float4 (aliases wt lower half)       off 33280
//   ps   : [64] x 33 float4 (aliases wt upper half)       off 41728
// total 50176 floats = 200704 bytes

__global__ void __launch_bounds__(512, 1)
fused_attn_kernel(const float* __restrict__ conv_feat,
                  const float* __restrict__ trans_feat,
                  float* __restrict__ out)
{
    extern __shared__ float sm[];
    float* feat = sm;
    float4* feat4 = (float4*)sm;                    // stride 17
    ulonglong2* qkvu  = (ulonglong2*)(sm + 8704);   // stride 96 per token
    ulonglong2* wtu   = (ulonglong2*)(sm + 33280);  // stride 33 per c
    ulonglong2* outsu = (ulonglong2*)(sm + 33280);  // stride 33 per token
    ulonglong2* psu   = (ulonglong2*)(sm + 41728);  // stride 33 per channel
    float4* wt4 = (float4*)(sm + 33280);
    float4* ps4 = (float4*)(sm + 41728);

    const int tid = threadIdx.x;
    const int wb = blockIdx.x;
    const int base = ((wb >> 8) * 4) * 4096 + (((wb >> 4) & 15) * 4) * 64 + (wb & 15) * 4;

    // ---- Phase 1: load cf/tf window tiles (channel-major [c][t]) ----
    #pragma unroll
    for (int k = 0; k < 4; k++) {
        int v = k * 512 + tid;              // 0..2047 float4s
        int vv = v & 1023;
        int c = vv >> 4;
        int r16 = vv & 15;                  // (dz,dy)
        const float* src = (v < 1024) ? conv_feat : trans_feat;
        float4 val = *(const float4*)(src + (size_t)c * VOL + base + (r16 >> 2) * 4096 + (r16 & 3) * 64);
        int row = (v < 1024) ? c : (64 + c);
        feat4[row * 17 + r16] = val;
    }
    __syncthreads();

    // ---- Phase 2: qkv[t][o] = sum_c WQKVT[c][o] * feat[c][t] + QB[o] ----
    // warp = (token-quarter tq, o-quarter oq); lane = (lx: token sub, ly: o sub)
    const int wid  = tid >> 5, lane = tid & 31;
    const int tq = wid & 3, oq = wid >> 2;
    const int lx = lane & 3, ly = lane >> 2;
    const int txg = tq * 4 + lx;            // token group (4 tokens), 0..15
    const int sxp = txg & 7;                // swizzle key = (t>>2)&7
    const float4* gW4 = (const float4*)g_WQKVT;  // [c][96] float4

    for (int ob = 0; ob < 384; ob += 128) {
        // stage weight chunk: wt4[c*33 + o4] = WQKVT4[c*96 + ob/4 + o4]
        #pragma unroll
        for (int k = 0; k < 8; k++) {
            int f = k * 512 + tid;          // 0..4095
            int c = f >> 5, o4 = f & 31;
            wt4[c * 33 + o4] = gW4[c * 96 + (ob >> 2) + o4];
        }
        __syncthreads();

        // 8 outputs (2 pairs) x 4 tokens per thread
        u64 acc[2][4];
        {
            float4 qb4 = *(const float4*)(g_QB + ob + oq * 32 + ly * 4);
            u64 b0 = pk2(qb4.x, qb4.y), b1 = pk2(qb4.z, qb4.w);
            #pragma unroll
            for (int m = 0; m < 4; m++) { acc[0][m] = b0; acc[1][m] = b1; }
        }
        #pragma unroll 4
        for (int c = 0; c < 128; c++) {
            float4 fv = feat4[c * 17 + txg];
            ulonglong2 wv = wtu[c * 33 + oq * 8 + ly];   // pairs (o0,o1),(o2,o3)
            u64 d0 = pk2(fv.x, fv.x), d1 = pk2(fv.y, fv.y);
            u64 d2 = pk2(fv.z, fv.z), d3 = pk2(fv.w, fv.w);
            fma2(acc[0][0], wv.x, d0); fma2(acc[1][0], wv.y, d0);
            fma2(acc[0][1], wv.x, d1); fma2(acc[1][1], wv.y, d1);
            fma2(acc[0][2], wv.x, d2); fma2(acc[1][2], wv.y, d2);
            fma2(acc[0][3], wv.x, d3); fma2(acc[1][3], wv.y, d3);
        }
        // swizzled conflict-free 16B stores
        {
            int u = (ob >> 2) + oq * 8 + ly;
            #pragma unroll
            for (int m = 0; m < 4; m++) {
                int t = txg * 4 + m;
                ulonglong2 st;
                st.x = acc[0][m]; st.y = acc[1][m];
                qkvu[t * 96 + (u ^ sxp)] = st;
            }
        }
        __syncthreads();
    }

    // ---- Phase 3: attention, 2 threads per (head,row), j-range split ----
    {
        const int jh  = tid & 1;           // j half: [jh*32, jh*32+32)
        const int idx = tid >> 1;
        const int h   = idx >> 6;          // warp-uniform
        const int ii  = idx & 63;
        const int isw = (ii >> 2) & 7;
        u64 qvp[16];                       // q pairs along d
        #pragma unroll
        for (int d4 = 0; d4 < 8; d4++) {
            ulonglong2 q = qkvu[ii * 96 + ((h * 8 + d4) ^ isw)];
            qvp[d4 * 2] = q.x; qvp[d4 * 2 + 1] = q.y;
        }
        float sc[32];
        const float4* brow4 = (const float4*)(g_BIAS + (h * 64 + ii) * 64 + jh * 32);
        #pragma unroll
        for (int j4 = 0; j4 < 8; j4++) {
            float4 b = brow4[j4];
            sc[j4 * 4 + 0] = b.x; sc[j4 * 4 + 1] = b.y;
            sc[j4 * 4 + 2] = b.z; sc[j4 * 4 + 3] = b.w;
        }
        const float scale = 0.17677669529663688f;  // 32^-0.5
        float rowmax = -1e30f;
        #pragma unroll
        for (int jj = 0; jj < 32; jj++) {
            int j = jh * 32 + jj;
            int jsw = (j >> 2) & 7;
            u64 a0 = 0ull, a1 = 0ull;
            #pragma unroll
            for (int d4 = 0; d4 < 8; d4++) {
                ulonglong2 kk = qkvu[j * 96 + ((32 + h * 8 + d4) ^ jsw)];
                fma2(a0, qvp[d4 * 2], kk.x);
                fma2(a1, qvp[d4 * 2 + 1], kk.y);
            }
            float l0, h0, l1, h1;
            upk2(a0, l0, h0); upk2(a1, l1, h1);
            float a = (l0 + h0) + (l1 + h1);
            sc[jj] = fmaf(a, scale, sc[jj]);
            rowmax = fmaxf(rowmax, sc[jj]);
        }
        rowmax = fmaxf(rowmax, __shfl_xor_sync(0xFFFFFFFFu, rowmax, 1));
        float ssum = 0.f;
        #pragma unroll
        for (int jj = 0; jj < 32; jj++) {
            sc[jj] = __expf(sc[jj] - rowmax);
            ssum += sc[jj];
        }
        ssum += __shfl_xor_sync(0xFFFFFFFFu, ssum, 1);
        float inv = 1.f / ssum;
        u64 ovp[16];
        #pragma unroll
        for (int d = 0; d < 16; d++) ovp[d] = 0ull;
        #pragma unroll
        for (int jj = 0; jj < 32; jj++) {
            int j = jh * 32 + jj;
            int jsw = (j >> 2) & 7;
            u64 p2 = pk2(sc[jj], sc[jj]);
            #pragma unroll
            for (int d4 = 0; d4 < 8; d4++) {
                ulonglong2 vv = qkvu[j * 96 + ((64 + h * 8 + d4) ^ jsw)];
                fma2(ovp[d4 * 2], p2, vv.x);
                fma2(ovp[d4 * 2 + 1], p2, vv.y);
            }
        }
        // combine partner halves (adjacent lanes)
        #pragma unroll
        for (int d = 0; d < 16; d++)
            ovp[d] = add2(ovp[d], __shfl_xor_sync(0xFFFFFFFFu, ovp[d], 1));
        u64 inv2 = pk2(inv, inv);
        // even thread stores d4 0..3, odd stores 4..7
        #pragma unroll
        for (int d4p = 0; d4p < 4; d4p++) {
            int d4 = jh * 4 + d4p;
            ulonglong2 st;
            st.x = mul2(ovp[d4 * 2], inv2);
            st.y = mul2(ovp[d4 * 2 + 1], inv2);
            outsu[ii * 33 + h * 8 + d4] = st;
        }
    }

    // stage P tile (ps region disjoint from outs & qkv)
    #pragma unroll
    for (int k = 0; k < 4; k++) {
        int f = k * 512 + tid;              // 0..2047
        ps4[(f >> 5) * 33 + (f & 31)] = *((const float4*)g_P + f);
    }
    __syncthreads();

    // ---- Phase 4: final[t][c] = sum_k outs[t][k]*P[c][k] + PB[c] + conv_feat[c][t] ----
    // executed by tid<256: 4 tokens (t = m*16+tx) x 4 channels (c = ty*4+r) per thread
    if (tid < 256) {
        const int tx = tid & 15;
        const int ty = tid >> 4;
        u64 acc2[4][4];
        #pragma unroll
        for (int r = 0; r < 4; r++)
            #pragma unroll
            for (int m = 0; m < 4; m++) acc2[r][m] = 0ull;

        #pragma unroll 4
        for (int k4 = 0; k4 < 32; k4++) {
            ulonglong2 pr[4], ovv[4];
            #pragma unroll
            for (int r = 0; r < 4; r++) pr[r] = psu[(ty * 4 + r) * 33 + k4];
            #pragma unroll
            for (int m = 0; m < 4; m++) ovv[m] = outsu[(m * 16 + tx) * 33 + k4];
            #pragma unroll
            for (int r = 0; r < 4; r++)
                #pragma unroll
                for (int m = 0; m < 4; m++) {
                    fma2(acc2[r][m], pr[r].x, ovv[m].x);
                    fma2(acc2[r][m], pr[r].y, ovv[m].y);
                }
        }
        int dy = tx >> 2, dx = tx & 3;
        #pragma unroll
        for (int r = 0; r < 4; r++) {
            int c = ty * 4 + r;
            float pb = g_PB[c];
            #pragma unroll
            for (int m = 0; m < 4; m++) {
                int t = m * 16 + tx;
                float lo, hi;
                upk2(acc2[r][m], lo, hi);
                float cf = feat[c * 68 + t];
                out[(size_t)c * VOL + base + m * 4096 + dy * 64 + dx] = (lo + hi) + pb + cf;
            }
        }
    }
}

// ---------------- launch ----------------
extern "C" void kernel_launch(void* const* d_in, const int* in_sizes, int n_in,
                              void* d_out, int out_size)
{
    const float* conv_feat  = (const float*)d_in[0];
    const float* trans_feat = (const float*)d_in[1];
    const float* conv_w     = (const float*)d_in[2];
    const float* conv_b     = (const float*)d_in[3];
    const float* trans_w    = (const float*)d_in[4];
    const float* trans_b    = (const float*)d_in[5];
    const float* qkv_w      = (const float*)d_in[6];
    const float* qkv_b      = (const float*)d_in[7];
    const float* proj_w     = (const float*)d_in[8];
    const float* proj_b     = (const float*)d_in[9];
    const float* table      = (const float*)d_in[10];
    const int*   ridx       = (const int*)d_in[11];
    float* o = (float*)d_out;

    cudaFuncSetAttribute(fused_attn_kernel, cudaFuncAttributeMaxDynamicSharedMemorySize, 200704);

    prep_kernel<<<290, 256>>>(conv_w, conv_b, trans_w, trans_b,
                              qkv_w, qkv_b, proj_w, proj_b, table, ridx);
    fused_attn_kernel<<<4096, 512, 200704>>>(conv_feat, trans_feat, o);
}

// round 7
// speedup vs baseline: 1.5008x; 1.4237x over previous
#include <cuda_runtime.h>

#define VOL 262144   // 64*64*64 voxels

typedef unsigned long long u64;

__device__ __forceinline__ u64 pk2(float lo, float hi) {
    u64 r; asm("mov.b64 %0,{%1,%2};" : "=l"(r) : "f"(lo), "f"(hi)); return r;
}
__device__ __forceinline__ void upk2(u64 v, float& lo, float& hi) {
    asm("mov.b64 {%0,%1},%2;" : "=f"(lo), "=f"(hi) : "l"(v));
}
__device__ __forceinline__ void fma2(u64& d, u64 a, u64 b) {
    asm("fma.rn.f32x2 %0,%1,%2,%0;" : "+l"(d) : "l"(a), "l"(b));
}

// ---------------- device-global precomputed weights (scratch; no allocs) ----------------
__device__ __align__(16) float g_WQKVT[128 * 384]; // folded qkv weights TRANSPOSED: [c][o] (q rows pre-scaled)
__device__ __align__(16) float g_QB[384];          // folded qkv bias (q part pre-scaled)
__device__ __align__(16) float g_P[64 * 128];      // proj_w[:64] + proj_w[64:]  [c][k]
__device__ float g_PB[64];                         // proj_b[:64] + proj_b[64:]
__device__ __align__(16) float g_BIAS[4 * 64 * 64];// dense rel-pos bias [h][i][j]

// ---------------- prep kernel ----------------
__global__ void prep_kernel(const float* __restrict__ conv_w, const float* __restrict__ conv_b,
                            const float* __restrict__ trans_w, const float* __restrict__ trans_b,
                            const float* __restrict__ qkv_w, const float* __restrict__ qkv_b,
                            const float* __restrict__ proj_w, const float* __restrict__ proj_b,
                            const float* __restrict__ table, const int* __restrict__ ridx)
{
    const float SCALE = 0.17677669529663688f;  // 32^-0.5
    int id = blockIdx.x * blockDim.x + threadIdx.x;
    if (id < 49152) {                       // WQKVT[c][o]
        int c = id / 384, o = id % 384;
        float s = 0.f;
        if (c < 64) {
            const float* qw = qkv_w + o * 128;
            #pragma unroll 8
            for (int m = 0; m < 64; m++) s += qw[m] * conv_w[m * 64 + c];
        } else {
            const float* qw = qkv_w + o * 128 + 64;
            int cc = c - 64;
            #pragma unroll 8
            for (int m = 0; m < 64; m++) s += qw[m] * trans_w[m * 64 + cc];
        }
        if (o < 128) s *= SCALE;            // fold attention scale into q
        g_WQKVT[id] = s;
    } else if (id < 49536) {                // QB
        int o = id - 49152;
        float s = qkv_b[o];
        const float* qw = qkv_w + o * 128;
        #pragma unroll 8
        for (int m = 0; m < 64; m++) s += qw[m] * conv_b[m] + qw[64 + m] * trans_b[m];
        if (o < 128) s *= SCALE;
        g_QB[o] = s;
    } else if (id < 57728) {                // P[c][k]
        int p = id - 49536;
        int c = p >> 7, k = p & 127;
        g_P[p] = proj_w[c * 128 + k] + proj_w[(c + 64) * 128 + k];
    } else if (id < 57792) {                // PB
        int c = id - 57728;
        g_PB[c] = proj_b[c] + proj_b[c + 64];
    } else if (id < 74176) {                // BIAS[h][i][j]
        int x = id - 57792;
        int h = x >> 12, ij = x & 4095;
        g_BIAS[x] = table[ridx[ij] * 4 + h];
    }
}

// ---------------- fused per-window kernel (256 threads) ----------------
// smem layout (floats):
//   feat : [128] x 17 float4             @ 0      .. 8704
//   qT   : [256 o][64 t] chunk-swizzled  @ 8704   .. 25088   (q rows 0-127, k rows 128-255)
//   vTok : [64 t] x 33 ulonglong2        @ 25088  .. 33536   (v token-major, unit-swizzled)
//   wt   : [128 c] x 33 float4           @ 33536  .. 50432   (phase2 weight tile)
//   PT   : [4 h][64 j][64 i] swizzled    @ 33536  .. 49920   (aliases wt, after sync)
//   ps   : [64] x 33 float4              @ 33536  .. 41984   (aliases PT, after sync)
//   outs : [64] x 33 ulonglong2          @ 8704   .. 17152   (aliases qT, after sync)
// total 50432 floats = 201728 bytes

__global__ void __launch_bounds__(256, 1)
fused_attn_kernel(const float* __restrict__ conv_feat,
                  const float* __restrict__ trans_feat,
                  float* __restrict__ out)
{
    extern __shared__ float sm[];
    float* feat = sm;
    float4* feat4 = (float4*)sm;                     // stride 17
    float* qT = sm + 8704;                           // [o][64]
    ulonglong2* vu = (ulonglong2*)(sm + 25088);      // stride 33 per token
    float4* wt4 = (float4*)(sm + 33536);             // stride 33 per c
    ulonglong2* wtu = (ulonglong2*)(sm + 33536);
    float* smPT = sm + 33536;                        // [h][j][64]
    float4* ps4 = (float4*)(sm + 33536);             // stride 33
    ulonglong2* psu = (ulonglong2*)(sm + 33536);
    float* outsf = sm + 8704;                        // [t][132]
    ulonglong2* outsu = (ulonglong2*)(sm + 8704);    // stride 33

    const int tid = threadIdx.x;
    const int wb = blockIdx.x;
    const int base = ((wb >> 8) * 4) * 4096 + (((wb >> 4) & 15) * 4) * 64 + (wb & 15) * 4;

    // ---- Phase 1: load cf/tf window tiles (channel-major [c][t]) ----
    #pragma unroll
    for (int k = 0; k < 8; k++) {
        int v = k * 256 + tid;
        int vv = v & 1023;
        int c = vv >> 4;
        int r16 = vv & 15;
        const float* src = (v < 1024) ? conv_feat : trans_feat;
        float4 val = *(const float4*)(src + (size_t)c * VOL + base + (r16 >> 2) * 4096 + (r16 & 3) * 64);
        int row = (v < 1024) ? c : (64 + c);
        feat4[row * 17 + r16] = val;
    }
    __syncthreads();

    // ---- Phase 2: qkv projections; q/k stored dim-major, v token-major ----
    const int tx = tid & 15;   // token group (4 tokens: t = tx*4+m)
    const int ty = tid >> 4;   // output group (8 outputs per 128-chunk)
    const int sx = tx & 7;
    const float4* gW4 = (const float4*)g_WQKVT;  // [c][96] float4

    #pragma unroll
    for (int chunk = 0; chunk < 3; chunk++) {
        const int ob = chunk * 128;
        #pragma unroll
        for (int k = 0; k < 16; k++) {
            int f = k * 256 + tid;
            int c = f >> 5, o4 = f & 31;
            wt4[c * 33 + o4] = gW4[c * 96 + (ob >> 2) + o4];
        }
        __syncthreads();

        u64 acc[4][4];   // [o-pair][token m]
        {
            float qb[8];
            #pragma unroll
            for (int r = 0; r < 8; r++) qb[r] = g_QB[ob + ty * 8 + r];
            #pragma unroll
            for (int op = 0; op < 4; op++) {
                u64 b2 = pk2(qb[op * 2], qb[op * 2 + 1]);
                acc[op][0] = b2; acc[op][1] = b2; acc[op][2] = b2; acc[op][3] = b2;
            }
        }
        #pragma unroll 4
        for (int c = 0; c < 128; c++) {
            float4 fv = feat4[c * 17 + tx];
            ulonglong2 wv0 = wtu[c * 33 + ty * 2];
            ulonglong2 wv1 = wtu[c * 33 + ty * 2 + 1];
            u64 d0 = pk2(fv.x, fv.x), d1 = pk2(fv.y, fv.y);
            u64 d2 = pk2(fv.z, fv.z), d3 = pk2(fv.w, fv.w);
            fma2(acc[0][0], wv0.x, d0); fma2(acc[1][0], wv0.y, d0);
            fma2(acc[2][0], wv1.x, d0); fma2(acc[3][0], wv1.y, d0);
            fma2(acc[0][1], wv0.x, d1); fma2(acc[1][1], wv0.y, d1);
            fma2(acc[2][1], wv1.x, d1); fma2(acc[3][1], wv1.y, d1);
            fma2(acc[0][2], wv0.x, d2); fma2(acc[1][2], wv0.y, d2);
            fma2(acc[2][2], wv1.x, d2); fma2(acc[3][2], wv1.y, d2);
            fma2(acc[0][3], wv0.x, d3); fma2(acc[1][3], wv0.y, d3);
            fma2(acc[2][3], wv1.x, d3); fma2(acc[3][3], wv1.y, d3);
        }
        if (chunk < 2) {
            // q/k: store dim-major qT[o][t], token-chunks XOR-swizzled by (o>>3)&7
            float fa[8][4];
            #pragma unroll
            for (int op = 0; op < 4; op++)
                #pragma unroll
                for (int m = 0; m < 4; m++)
                    upk2(acc[op][m], fa[op * 2][m], fa[op * 2 + 1][m]);
            #pragma unroll
            for (int r = 0; r < 8; r++) {
                int o = ob + ty * 8 + r;
                int key = (o >> 3) & 7;
                *(float4*)(qT + o * 64 + ((tx ^ key) << 2)) =
                    make_float4(fa[r][0], fa[r][1], fa[r][2], fa[r][3]);
            }
        } else {
            // v: token-major vTok[t][32 units], units XOR-swizzled by (t>>2)&7
            #pragma unroll
            for (int r4 = 0; r4 < 2; r4++) {
                int u = ty * 2 + r4;
                #pragma unroll
                for (int m = 0; m < 4; m++) {
                    int t = tx * 4 + m;
                    ulonglong2 st;
                    st.x = acc[r4 * 2 + 0][m];
                    st.y = acc[r4 * 2 + 1][m];
                    vu[t * 33 + (u ^ sx)] = st;
                }
            }
        }
        __syncthreads();
    }

    // ---- Phase 3: attention as two outer-product GEMMs ----
    const int h  = tid >> 6;           // head (warp-pair uniform)
    const int u6 = tid & 63;
    const int a  = u6 >> 3, b = u6 & 7;
    const int i0 = a * 8, j0 = b * 8;
    float inv[8];

    {
        // S[i][j] = sum_d q[i,d]*k[j,d] + bias   (q pre-scaled)
        u64 sp[8][4];  // packed along j
        #pragma unroll
        for (int i = 0; i < 8; i++) {
            const float4* bb = (const float4*)(g_BIAS + (h * 64 + i0 + i) * 64 + j0);
            float4 b0 = bb[0], b1 = bb[1];
            sp[i][0] = pk2(b0.x, b0.y); sp[i][1] = pk2(b0.z, b0.w);
            sp[i][2] = pk2(b1.x, b1.y); sp[i][3] = pk2(b1.z, b1.w);
        }
        #pragma unroll 8
        for (int d = 0; d < 32; d++) {
            int key = ((h * 32 + d) >> 3) & 7;
            const float* qrow = qT + (h * 32 + d) * 64;
            const float* krow = qT + (128 + h * 32 + d) * 64;
            float4 q0 = *(const float4*)(qrow + (((2 * a + 0) ^ key) << 2));
            float4 q1 = *(const float4*)(qrow + (((2 * a + 1) ^ key) << 2));
            ulonglong2 kA = *(const ulonglong2*)(krow + (((2 * b + 0) ^ key) << 2));
            ulonglong2 kB = *(const ulonglong2*)(krow + (((2 * b + 1) ^ key) << 2));
            u64 kp0 = kA.x, kp1 = kA.y, kp2 = kB.x, kp3 = kB.y;
            float qf[8] = {q0.x, q0.y, q0.z, q0.w, q1.x, q1.y, q1.z, q1.w};
            #pragma unroll
            for (int i = 0; i < 8; i++) {
                u64 qd = pk2(qf[i], qf[i]);
                fma2(sp[i][0], qd, kp0); fma2(sp[i][1], qd, kp1);
                fma2(sp[i][2], qd, kp2); fma2(sp[i][3], qd, kp3);
            }
        }
        // softmax over rows i (reduce across the 8 b-lanes)
        float s[8][8];
        #pragma unroll
        for (int i = 0; i < 8; i++) {
            upk2(sp[i][0], s[i][0], s[i][1]); upk2(sp[i][1], s[i][2], s[i][3]);
            upk2(sp[i][2], s[i][4], s[i][5]); upk2(sp[i][3], s[i][6], s[i][7]);
        }
        #pragma unroll
        for (int i = 0; i < 8; i++) {
            float m = s[i][0];
            #pragma unroll
            for (int j = 1; j < 8; j++) m = fmaxf(m, s[i][j]);
            m = fmaxf(m, __shfl_xor_sync(0xFFFFFFFFu, m, 1));
            m = fmaxf(m, __shfl_xor_sync(0xFFFFFFFFu, m, 2));
            m = fmaxf(m, __shfl_xor_sync(0xFFFFFFFFu, m, 4));
            float sum = 0.f;
            #pragma unroll
            for (int j = 0; j < 8; j++) { s[i][j] = __expf(s[i][j] - m); sum += s[i][j]; }
            sum += __shfl_xor_sync(0xFFFFFFFFu, sum, 1);
            sum += __shfl_xor_sync(0xFFFFFFFFu, sum, 2);
            sum += __shfl_xor_sync(0xFFFFFFFFu, sum, 4);
            inv[i] = 1.f / sum;
        }
        // store P transposed: PT[h][j][i], i-chunks XOR-swizzled by (j>>3)&7 (== b)
        #pragma unroll
        for (int jj = 0; jj < 8; jj++) {
            float* prow = smPT + h * 4096 + (j0 + jj) * 64;
            *(float4*)(prow + (((2 * a + 0) ^ b) << 2)) =
                make_float4(s[0][jj], s[1][jj], s[2][jj], s[3][jj]);
            *(float4*)(prow + (((2 * a + 1) ^ b) << 2)) =
                make_float4(s[4][jj], s[5][jj], s[6][jj], s[7][jj]);
        }
    }
    __syncthreads();

    {
        // O[i][d] = sum_j P[i][j]*v[j][d]; thread: 4 i-pairs x 4 d-cols (unit h*8+b)
        u64 o_[4][4];
        #pragma unroll
        for (int ip = 0; ip < 4; ip++)
            #pragma unroll
            for (int dc = 0; dc < 4; dc++) o_[ip][dc] = 0ull;

        #pragma unroll 8
        for (int j = 0; j < 64; j++) {
            const float* prow = smPT + h * 4096 + j * 64;
            int kj = (j >> 3) & 7;
            ulonglong2 pA = *(const ulonglong2*)(prow + (((2 * a + 0) ^ kj) << 2));
            ulonglong2 pB = *(const ulonglong2*)(prow + (((2 * a + 1) ^ kj) << 2));
            int kv = (j >> 2) & 7;
            ulonglong2 vv = vu[j * 33 + ((h * 8 + b) ^ kv)];
            float v0, v1, v2, v3;
            upk2(vv.x, v0, v1); upk2(vv.y, v2, v3);
            u64 vd0 = pk2(v0, v0), vd1 = pk2(v1, v1), vd2 = pk2(v2, v2), vd3 = pk2(v3, v3);
            u64 pp0 = pA.x, pp1 = pA.y, pp2 = pB.x, pp3 = pB.y;
            fma2(o_[0][0], pp0, vd0); fma2(o_[0][1], pp0, vd1);
            fma2(o_[0][2], pp0, vd2); fma2(o_[0][3], pp0, vd3);
            fma2(o_[1][0], pp1, vd0); fma2(o_[1][1], pp1, vd1);
            fma2(o_[1][2], pp1, vd2); fma2(o_[1][3], pp1, vd3);
            fma2(o_[2][0], pp2, vd0); fma2(o_[2][1], pp2, vd1);
            fma2(o_[2][2], pp2, vd2); fma2(o_[2][3], pp2, vd3);
            fma2(o_[3][0], pp3, vd0); fma2(o_[3][1], pp3, vd1);
            fma2(o_[3][2], pp3, vd2); fma2(o_[3][3], pp3, vd3);
        }
        __syncthreads();   // all PT/vTok/qT reads done; safe to overwrite below

        // normalize + store outs[t][k] (k-unit = h*8+b), rows i0+2ip, i0+2ip+1
        #pragma unroll
        for (int ip = 0; ip < 4; ip++) {
            float oa[4], obv[4];
            upk2(o_[ip][0], oa[0], obv[0]); upk2(o_[ip][1], oa[1], obv[1]);
            upk2(o_[ip][2], oa[2], obv[2]); upk2(o_[ip][3], oa[3], obv[3]);
            float ia = inv[ip * 2], ib = inv[ip * 2 + 1];
            int iA = i0 + ip * 2;
            *(float4*)(outsf + iA * 132 + (h * 8 + b) * 4) =
                make_float4(oa[0] * ia, oa[1] * ia, oa[2] * ia, oa[3] * ia);
            *(float4*)(outsf + (iA + 1) * 132 + (h * 8 + b) * 4) =
                make_float4(obv[0] * ib, obv[1] * ib, obv[2] * ib, obv[3] * ib);
        }
    }

    // stage proj tile (overlays PT; PT dead after post-PV sync)
    #pragma unroll
    for (int k = 0; k < 8; k++) {
        int f = k * 256 + tid;
        ps4[(f >> 5) * 33 + (f & 31)] = *((const float4*)g_P + f);
    }
    __syncthreads();

    // ---- Phase 4: final[t][c] = sum_k outs[t][k]*P[c][k] + PB[c] + conv_feat[c][t] ----
    {
        u64 acc2[4][4];
        #pragma unroll
        for (int r = 0; r < 4; r++)
            #pragma unroll
            for (int m = 0; m < 4; m++) acc2[r][m] = 0ull;

        #pragma unroll 4
        for (int k4 = 0; k4 < 32; k4++) {
            ulonglong2 pr[4], ovv[4];
            #pragma unroll
            for (int r = 0; r < 4; r++) pr[r] = psu[(ty * 4 + r) * 33 + k4];
            #pragma unroll
            for (int m = 0; m < 4; m++) ovv[m] = outsu[(m * 16 + tx) * 33 + k4];
            #pragma unroll
            for (int r = 0; r < 4; r++)
                #pragma unroll
                for (int m = 0; m < 4; m++) {
                    fma2(acc2[r][m], pr[r].x, ovv[m].x);
                    fma2(acc2[r][m], pr[r].y, ovv[m].y);
                }
        }
        int dy = tx >> 2, dx = tx & 3;
        #pragma unroll
        for (int r = 0; r < 4; r++) {
            int c = ty * 4 + r;
            float pb = g_PB[c];
            #pragma unroll
            for (int m = 0; m < 4; m++) {
                int t = m * 16 + tx;
                float lo, hi;
                upk2(acc2[r][m], lo, hi);
                float cf = feat[c * 68 + t];
                out[(size_t)c * VOL + base + m * 4096 + dy * 64 + dx] = (lo + hi) + pb + cf;
            }
        }
    }
}

// ---------------- launch ----------------
extern "C" void kernel_launch(void* const* d_in, const int* in_sizes, int n_in,
                              void* d_out, int out_size)
{
    const float* conv_feat  = (const float*)d_in[0];
    const float* trans_feat = (const float*)d_in[1];
    const float* conv_w     = (const float*)d_in[2];
    const float* conv_b     = (const float*)d_in[3];
    const float* trans_w    = (const float*)d_in[4];
    const float* trans_b    = (const float*)d_in[5];
    const float* qkv_w      = (const float*)d_in[6];
    const float* qkv_b      = (const float*)d_in[7];
    const float* proj_w     = (const float*)d_in[8];
    const float* proj_b     = (const float*)d_in[9];
    const float* table      = (const float*)d_in[10];
    const int*   ridx       = (const int*)d_in[11];
    float* o = (float*)d_out;

    cudaFuncSetAttribute(fused_attn_kernel, cudaFuncAttributeMaxDynamicSharedMemorySize, 201728);

    prep_kernel<<<290, 256>>>(conv_w, conv_b, trans_w, trans_b,
                              qkv_w, qkv_b, proj_w, proj_b, table, ridx);
    fused_attn_kernel<<<4096, 256, 201728>>>(conv_feat, trans_feat, o);
}